// round 15
// baseline (speedup 1.0000x reference)
#include <cuda_runtime.h>
#include <cuda_fp16.h>
#include <math.h>
#include <stdint.h>

#define B_   4
#define T_   2048
#define C_   1024
#define H_   16
#define D_   64
#define M_   (B_ * T_)           // 8192 rows
#define LN_EPS 1e-5f
#define QSCALE (0.125f * 1.4426950408889634f)   // 1/sqrt(D) * log2(e)

// ---------------- scratch (static device globals; no allocation) -----------
__device__ __align__(128) float g_att[(size_t)M_ * C_];
__device__ __align__(128) float g_x1 [(size_t)M_ * C_];
__device__ __align__(128) float g_mlp[(size_t)M_ * C_];
__device__ __align__(128) __half g_qkvh[(size_t)M_ * 3 * C_];
__device__ __align__(128) __half g_ah [(size_t)M_ * C_];        // A (x / x1) fp16
__device__ __align__(128) __half g_ah2[(size_t)M_ * 4 * C_];    // gelu(h) fp16
__device__ __align__(128) __half g_b0 [(size_t)3 * C_ * C_];    // w_qkv^T fp16
__device__ __align__(128) __half g_b1 [(size_t)4 * C_ * C_];    // w_fc1^T fp16
__device__ __align__(128) __half g_b2 [(size_t)4 * C_ * C_];    // w_fc2^T fp16

__device__ __forceinline__ float gelu_exact(float x) {
    return 0.5f * x * (1.0f + erff(x * 0.70710678118654752440f));
}

// ---------------- PTX helpers ----------------------------------------------
__device__ __forceinline__ uint32_t smem_u32(const void* p) {
    uint32_t a;
    asm("{ .reg .u64 t; cvta.to.shared.u64 t, %1; cvt.u32.u64 %0, t; }" : "=r"(a) : "l"(p));
    return a;
}
#define CP16(s, g) asm volatile("cp.async.cg.shared.global [%0], [%1], 16;" :: "r"(s), "l"(g))
#define CP_COMMIT() asm volatile("cp.async.commit_group;" ::: "memory")
#define CP_WAIT0()  asm volatile("cp.async.wait_group 0;" ::: "memory")
template <int N>
__device__ __forceinline__ void cp_wait() {
    asm volatile("cp.async.wait_group %0;" :: "n"(N) : "memory");
}

__device__ __forceinline__ void ldsm4(uint32_t& r0, uint32_t& r1,
                                      uint32_t& r2, uint32_t& r3, uint32_t addr) {
    asm volatile("ldmatrix.sync.aligned.m8n8.x4.shared.b16 {%0,%1,%2,%3}, [%4];"
                 : "=r"(r0), "=r"(r1), "=r"(r2), "=r"(r3) : "r"(addr));
}
__device__ __forceinline__ void ldsm4t(uint32_t& r0, uint32_t& r1,
                                       uint32_t& r2, uint32_t& r3, uint32_t addr) {
    asm volatile("ldmatrix.sync.aligned.m8n8.x4.trans.shared.b16 {%0,%1,%2,%3}, [%4];"
                 : "=r"(r0), "=r"(r1), "=r"(r2), "=r"(r3) : "r"(addr));
}
#define MMA16816(c, a, b)                                                     \
    asm("mma.sync.aligned.m16n8k16.row.col.f32.f16.f16.f32 "                  \
        "{%0,%1,%2,%3}, {%4,%5,%6,%7}, {%8,%9}, {%0,%1,%2,%3};"               \
        : "+f"((c)[0]), "+f"((c)[1]), "+f"((c)[2]), "+f"((c)[3])              \
        : "r"((a)[0]), "r"((a)[1]), "r"((a)[2]), "r"((a)[3]),                 \
          "r"((b)[0]), "r"((b)[1]))

__device__ __forceinline__ uint32_t pack_f16x2(float lo, float hi) {
    uint32_t r;
    asm("cvt.rn.f16x2.f32 %0, %1, %2;" : "=r"(r) : "f"(hi), "f"(lo));
    return r;
}

// ---------------- conversion kernels ----------------------------------------
__global__ void __launch_bounds__(256) round_act(
    const float* __restrict__ X, __half* __restrict__ Hh, size_t n4)
{
    size_t i = (size_t)blockIdx.x * blockDim.x + threadIdx.x;
    if (i >= n4) return;
    float4 v = ((const float4*)X)[i];
    ((uint32_t*)Hh)[2 * i]     = pack_f16x2(v.x, v.y);
    ((uint32_t*)Hh)[2 * i + 1] = pack_f16x2(v.z, v.w);
}

// All three weight transposes in one launch.
__global__ void __launch_bounds__(256) round_w_all(
    const float* __restrict__ W0, __half* __restrict__ B0,
    const float* __restrict__ W1, __half* __restrict__ B1,
    const float* __restrict__ W2, __half* __restrict__ B2)
{
    int bid = blockIdx.x;
    const float* W; __half* Bh; int K, N;
    if (bid < 3072)      { W = W0; Bh = B0; K = 1024; N = 3072; }
    else if (bid < 7168) { bid -= 3072; W = W1; Bh = B1; K = 1024; N = 4096; }
    else                 { bid -= 7168; W = W2; Bh = B2; K = 4096; N = 1024; }
    const int nbn = N / 32;
    const int n0 = (bid % nbn) * 32, k0 = (bid / nbn) * 32;

    __shared__ float t[32][33];
    const int tx = threadIdx.x & 31, ty = threadIdx.x >> 5;
#pragma unroll
    for (int r = 0; r < 4; r++)
        t[ty + r * 8][tx] = W[(size_t)(k0 + ty + r * 8) * N + n0 + tx];
    __syncthreads();
#pragma unroll
    for (int r = 0; r < 4; r++) {
        int nn = ty + r * 8;
        Bh[(size_t)(n0 + nn) * K + k0 + tx] = __float2half_rn(t[tx][nn]);
    }
}

// ---------------- HMMA fp16 GEMM (fp32 accum, 512 threads) ------------------
// C = A@B^T + bias.  CTA tile (128*MT)x128, 16 warps (4m x 4n).
// MT=2: 6-stage pipeline, 1 CTA/SM.  MT=1: 4-stage, 2 CTA/SM (FC2 wave fix).
// MODE 0: fp32 out; MODE 1: fp16 out, Q cols scaled QSCALE; MODE 2: gelu fp16.
#define GM_BK     32
#define GM_ROWB   80
#define GM_BOP    (128 * GM_ROWB)             // 10240

template <int MODE, int MT>
__global__ void __launch_bounds__(512, (MT == 1 ? 2 : 1)) gemm_mma(
    const __half* __restrict__ Ah, const __half* __restrict__ Bh,
    const float* __restrict__ bias, float* __restrict__ Cmat,
    __half* __restrict__ Oh, int N, int K)
{
    constexpr int ROWS   = 128 * MT;
    constexpr int MB     = 2 * MT;            // m-blocks per warp
    constexpr int AOP    = ROWS * GM_ROWB;
    constexpr int STAGE  = AOP + GM_BOP;
    constexpr int STAGES = (MT == 2 ? 6 : 4);

    extern __shared__ char smem[];
    const uint32_t sb = smem_u32(smem);
    const int tid  = threadIdx.x;
    const int lane = tid & 31;
    const int wid  = tid >> 5;                  // 0..15
    const int m0 = blockIdx.y * ROWS;
    const int n0 = blockIdx.x * 128;
    const int wm = (wid >> 2) * (MB * 16);
    const int wn = (wid & 3) * 32;

    const int nch = K / GM_BK;

    auto load_chunk = [&](int c) {
        const int kk = c * GM_BK;
        const uint32_t st = sb + (c % STAGES) * STAGE;
#pragma unroll
        for (int i = 0; i < MT; i++) {               // A: ROWS*4 x 16B units
            int u = tid + i * 512;
            int r = u >> 2, cc = u & 3;
            CP16(st + r * GM_ROWB + cc * 16, Ah + (size_t)(m0 + r) * K + kk + cc * 8);
        }
        {                                            // B: 512 x 16B units
            int r = tid >> 2, cc = tid & 3;
            CP16(st + AOP + r * GM_ROWB + cc * 16, Bh + (size_t)(n0 + r) * K + kk + cc * 8);
        }
    };

    float acc[MB][4][4];
#pragma unroll
    for (int i = 0; i < MB; i++)
#pragma unroll
        for (int j = 0; j < 4; j++)
#pragma unroll
            for (int t = 0; t < 4; t++) acc[i][j][t] = 0.f;

#pragma unroll
    for (int s = 0; s < STAGES - 1; s++) { load_chunk(s); CP_COMMIT(); }

    const int a_row = lane & 15;
    const int a_off = (lane >> 4) * 16;
    const int b_row = (lane & 7) + ((lane >> 4) << 3);
    const int b_off = ((lane >> 3) & 1) * 16;

    for (int k = 0; k < nch; k++) {
        cp_wait<STAGES - 2>();
        __syncthreads();
        if (k + STAGES - 1 < nch) load_chunk(k + STAGES - 1);
        CP_COMMIT();

        const uint32_t stA = sb + (k % STAGES) * STAGE;
        const uint32_t stB = stA + AOP;

#pragma unroll
        for (int ks = 0; ks < 2; ks++) {
            uint32_t ah[MB][4];
#pragma unroll
            for (int mb = 0; mb < MB; mb++) {
                uint32_t ad = stA + (wm + mb * 16 + a_row) * GM_ROWB + ks * 32 + a_off;
                ldsm4(ah[mb][0], ah[mb][1], ah[mb][2], ah[mb][3], ad);
            }
#pragma unroll
            for (int nbp = 0; nbp < 2; nbp++) {
                uint32_t bd = stB + (wn + nbp * 16 + b_row) * GM_ROWB + ks * 32 + b_off;
                uint32_t h0, h1, h2, h3;
                ldsm4(h0, h1, h2, h3, bd);
                uint32_t b0h[2] = {h0, h1}, b1h[2] = {h2, h3};
#pragma unroll
                for (int mb = 0; mb < MB; mb++) MMA16816(acc[mb][2 * nbp],     ah[mb], b0h);
#pragma unroll
                for (int mb = 0; mb < MB; mb++) MMA16816(acc[mb][2 * nbp + 1], ah[mb], b1h);
            }
        }
    }

    // ---- epilogue ----
    const int gr = lane >> 2;
    const int gc = (lane & 3) * 2;
#pragma unroll
    for (int mb = 0; mb < MB; mb++) {
#pragma unroll
        for (int nb = 0; nb < 4; nb++) {
            int row = m0 + wm + mb * 16 + gr;
            int col = n0 + wn + nb * 8 + gc;
            float b0 = __ldg(&bias[col]), b1 = __ldg(&bias[col + 1]);
            float v0 = acc[mb][nb][0] + b0, v1 = acc[mb][nb][1] + b1;
            float v2 = acc[mb][nb][2] + b0, v3 = acc[mb][nb][3] + b1;
            if (MODE == 0) {
                *(float2*)(Cmat + (size_t)row * N + col)       = make_float2(v0, v1);
                *(float2*)(Cmat + (size_t)(row + 8) * N + col) = make_float2(v2, v3);
            } else {
                if (MODE == 1 && col < C_) {
                    v0 *= QSCALE; v1 *= QSCALE; v2 *= QSCALE; v3 *= QSCALE;
                }
                if (MODE == 2) {
                    v0 = gelu_exact(v0); v1 = gelu_exact(v1);
                    v2 = gelu_exact(v2); v3 = gelu_exact(v3);
                }
                *(uint32_t*)(Oh + (size_t)row * N + col)       = pack_f16x2(v0, v1);
                *(uint32_t*)(Oh + (size_t)(row + 8) * N + col) = pack_f16x2(v2, v3);
            }
        }
    }
}

#define GM_SMEM2  (6 * (256 * GM_ROWB + GM_BOP))   // 184320 (MT=2)
#define GM_SMEM1  (4 * (128 * GM_ROWB + GM_BOP))   // 81920  (MT=1)

// ---------------- tensor-core causal flash attention (all fp16) -------------
#define AT_ROWB  144
#define AQ_T     (128 * AT_ROWB)             // 18432 (Q)
#define AK_T     (64 * AT_ROWB)              // 9216 per K/V operand
#define AT_STAGE (2 * AK_T)                  // Kh,Vh = 18432
#define AT_SMEM  (AQ_T + 2 * AT_STAGE)       // 55296

__global__ void __launch_bounds__(256, 2) attn_tc(
    const __half* __restrict__ qkvh, float* __restrict__ y)
{
    extern __shared__ char smem[];
    const uint32_t sb = smem_u32(smem);
    const int tid = threadIdx.x, lane = tid & 31, wid = tid >> 5;
    const int qb = (int)gridDim.x - 1 - (int)blockIdx.x;
    const int h = blockIdx.y, b = blockIdx.z;
    const int q0 = qb * 128;
    const int wq = wid * 16;
    const int gr = lane >> 2, gc = lane & 3;
    const int RS = 3 * C_;

    const __half* qh = qkvh + (size_t)b * T_ * RS + h * D_;
    const __half* kh = qh + C_;
    const __half* vh = qh + 2 * C_;

    const uint32_t QH  = sb;
    const uint32_t ST0 = sb + AQ_T;

#pragma unroll
    for (int i = 0; i < 4; i++) {
        int u = tid + i * 256;
        int r = u >> 3, c = u & 7;
        CP16(QH + r * AT_ROWB + c * 16, qh + (size_t)(q0 + r) * RS + c * 8);
    }

    auto load_tile = [&](int kt, int bufsel) {
        uint32_t st = ST0 + bufsel * AT_STAGE;
#pragma unroll
        for (int t = 0; t < 2; t++) {
            const __half* g = (t == 0 ? kh : vh);
#pragma unroll
            for (int i = 0; i < 2; i++) {
                int u = tid + i * 256;
                int r = u >> 3, c = u & 7;
                CP16(st + t * AK_T + r * AT_ROWB + c * 16, g + (size_t)(kt * 64 + r) * RS + c * 8);
            }
        }
    };
    load_tile(0, 0);
    CP_COMMIT();
    CP_WAIT0();
    __syncthreads();

    uint32_t qf[4][4];
    const int a_row = lane & 15, a_off = (lane >> 4) * 16;
#pragma unroll
    for (int ks = 0; ks < 4; ks++) {
        uint32_t ad = QH + (wq + a_row) * AT_ROWB + ks * 32 + a_off;
        ldsm4(qf[ks][0], qf[ks][1], qf[ks][2], qf[ks][3], ad);
    }

    float Oacc[8][4];
#pragma unroll
    for (int i = 0; i < 8; i++)
#pragma unroll
        for (int j = 0; j < 4; j++) Oacc[i][j] = 0.f;
    float m0 = -1e30f, m1 = -1e30f, l0 = 0.f, l1 = 0.f;

    const int nt = 2 * qb + 2;
    const int b_row = (lane & 7) + ((lane >> 4) << 3);
    const int b_off = ((lane >> 3) & 1) * 16;
    const int v_row = (lane & 7) + ((lane >> 3) & 1) * 8;
    const int v_off = (lane >> 4) * 16;

    for (int kt = 0; kt < nt; kt++) {
        if (kt + 1 < nt) { load_tile(kt + 1, (kt + 1) & 1); CP_COMMIT(); }
        const uint32_t st = ST0 + (kt & 1) * AT_STAGE;

        const bool active = (kt * 64) <= (q0 + wq + 15);
        if (active) {
            float sacc[8][4];
#pragma unroll
            for (int i = 0; i < 8; i++)
#pragma unroll
                for (int j = 0; j < 4; j++) sacc[i][j] = 0.f;

#pragma unroll
            for (int nbp = 0; nbp < 4; nbp++) {
#pragma unroll
                for (int ks = 0; ks < 4; ks++) {
                    uint32_t kd = st + (nbp * 16 + b_row) * AT_ROWB + ks * 32 + b_off;
                    uint32_t r0, r1, r2, r3;
                    ldsm4(r0, r1, r2, r3, kd);
                    uint32_t b0[2] = {r0, r1}, b1[2] = {r2, r3};
                    MMA16816(sacc[2 * nbp],     qf[ks], b0);
                    MMA16816(sacc[2 * nbp + 1], qf[ks], b1);
                }
            }

            if (kt * 64 + 63 > q0 + wq) {
                const int qg0 = q0 + wq + gr, qg1 = qg0 + 8;
#pragma unroll
                for (int nb = 0; nb < 8; nb++) {
                    int kg = kt * 64 + nb * 8 + 2 * gc;
                    if (kg     > qg0) sacc[nb][0] = -1e30f;
                    if (kg + 1 > qg0) sacc[nb][1] = -1e30f;
                    if (kg     > qg1) sacc[nb][2] = -1e30f;
                    if (kg + 1 > qg1) sacc[nb][3] = -1e30f;
                }
            }

            float mx0 = m0, mx1 = m1;
#pragma unroll
            for (int nb = 0; nb < 8; nb++) {
                mx0 = fmaxf(mx0, fmaxf(sacc[nb][0], sacc[nb][1]));
                mx1 = fmaxf(mx1, fmaxf(sacc[nb][2], sacc[nb][3]));
            }
            mx0 = fmaxf(mx0, __shfl_xor_sync(0xffffffffu, mx0, 1));
            mx0 = fmaxf(mx0, __shfl_xor_sync(0xffffffffu, mx0, 2));
            mx1 = fmaxf(mx1, __shfl_xor_sync(0xffffffffu, mx1, 1));
            mx1 = fmaxf(mx1, __shfl_xor_sync(0xffffffffu, mx1, 2));
            float al0 = exp2f(m0 - mx0), al1 = exp2f(m1 - mx1);
            m0 = mx0; m1 = mx1;
            float ls0 = 0.f, ls1 = 0.f;
#pragma unroll
            for (int nb = 0; nb < 8; nb++) {
                sacc[nb][0] = exp2f(sacc[nb][0] - mx0); ls0 += sacc[nb][0];
                sacc[nb][1] = exp2f(sacc[nb][1] - mx0); ls0 += sacc[nb][1];
                sacc[nb][2] = exp2f(sacc[nb][2] - mx1); ls1 += sacc[nb][2];
                sacc[nb][3] = exp2f(sacc[nb][3] - mx1); ls1 += sacc[nb][3];
            }
            l0 = l0 * al0 + ls0;
            l1 = l1 * al1 + ls1;
#pragma unroll
            for (int nb = 0; nb < 8; nb++) {
                Oacc[nb][0] *= al0; Oacc[nb][1] *= al0;
                Oacc[nb][2] *= al1; Oacc[nb][3] *= al1;
            }

#pragma unroll
            for (int kb = 0; kb < 4; kb++) {
                uint32_t ph[4];
                ph[0] = pack_f16x2(sacc[2 * kb][0],     sacc[2 * kb][1]);
                ph[1] = pack_f16x2(sacc[2 * kb][2],     sacc[2 * kb][3]);
                ph[2] = pack_f16x2(sacc[2 * kb + 1][0], sacc[2 * kb + 1][1]);
                ph[3] = pack_f16x2(sacc[2 * kb + 1][2], sacc[2 * kb + 1][3]);
#pragma unroll
                for (int nbp = 0; nbp < 4; nbp++) {
                    uint32_t vd = st + AK_T + (kb * 16 + v_row) * AT_ROWB + nbp * 32 + v_off;
                    uint32_t r0, r1, r2, r3;
                    ldsm4t(r0, r1, r2, r3, vd);
                    uint32_t v0[2] = {r0, r1}, v1[2] = {r2, r3};
                    MMA16816(Oacc[2 * nbp],     ph, v0);
                    MMA16816(Oacc[2 * nbp + 1], ph, v1);
                }
            }
        }

        CP_WAIT0();
        __syncthreads();
    }

    l0 += __shfl_xor_sync(0xffffffffu, l0, 1);
    l0 += __shfl_xor_sync(0xffffffffu, l0, 2);
    l1 += __shfl_xor_sync(0xffffffffu, l1, 1);
    l1 += __shfl_xor_sync(0xffffffffu, l1, 2);
    const float inv0 = 1.f / l0, inv1 = 1.f / l1;

    float* yb = y + ((size_t)b * T_ + q0 + wq) * C_ + h * D_;
#pragma unroll
    for (int nb = 0; nb < 8; nb++) {
        int col = nb * 8 + 2 * gc;
        *(float2*)(yb + (size_t)gr * C_ + col) =
            make_float2(Oacc[nb][0] * inv0, Oacc[nb][1] * inv0);
        *(float2*)(yb + (size_t)(gr + 8) * C_ + col) =
            make_float2(Oacc[nb][2] * inv1, Oacc[nb][3] * inv1);
    }
}

// ---------------- residual add + LayerNorm (+ optional fp16 out) -----------
template <bool SPLIT>
__global__ void __launch_bounds__(256) add_ln_kernel(
    const float* __restrict__ a, const float* __restrict__ bres,
    const float* __restrict__ g, const float* __restrict__ beta,
    float* __restrict__ out, __half* __restrict__ Oh)
{
    const int row = blockIdx.x;
    const int tid = threadIdx.x;

    const float4 av = ((const float4*)(a    + (size_t)row * C_))[tid];
    const float4 bv = ((const float4*)(bres + (size_t)row * C_))[tid];
    float4 v = make_float4(av.x + bv.x, av.y + bv.y, av.z + bv.z, av.w + bv.w);

    float s  = v.x + v.y + v.z + v.w;
    float sq = v.x * v.x + v.y * v.y + v.z * v.z + v.w * v.w;
#pragma unroll
    for (int off = 16; off; off >>= 1) {
        s  += __shfl_xor_sync(0xffffffffu, s,  off);
        sq += __shfl_xor_sync(0xffffffffu, sq, off);
    }
    __shared__ float ws[8], wsq[8];
    if ((tid & 31) == 0) { ws[tid >> 5] = s; wsq[tid >> 5] = sq; }
    __syncthreads();
    float tot = 0.f, totq = 0.f;
#pragma unroll
    for (int i = 0; i < 8; i++) { tot += ws[i]; totq += wsq[i]; }

    const float mu   = tot * (1.0f / C_);
    const float var  = totq * (1.0f / C_) - mu * mu;
    const float rstd = rsqrtf(var + LN_EPS);

    const float4 gv = ((const float4*)g)[tid];
    const float4 be = ((const float4*)beta)[tid];
    float4 o;
    o.x = (v.x - mu) * rstd * gv.x + be.x;
    o.y = (v.y - mu) * rstd * gv.y + be.y;
    o.z = (v.z - mu) * rstd * gv.z + be.z;
    o.w = (v.w - mu) * rstd * gv.w + be.w;
    ((float4*)(out + (size_t)row * C_))[tid] = o;
    if (SPLIT) {
        uint32_t* oh = (uint32_t*)(Oh + (size_t)row * C_);
        oh[2 * tid]     = pack_f16x2(o.x, o.y);
        oh[2 * tid + 1] = pack_f16x2(o.z, o.w);
    }
}

// ---------------- launcher --------------------------------------------------
extern "C" void kernel_launch(void* const* d_in, const int* in_sizes, int n_in,
                              void* d_out, int out_size)
{
    const float* x     = (const float*)d_in[0];
    const float* w_qkv = (const float*)d_in[1];
    const float* b_qkv = (const float*)d_in[2];
    const float* ln1_g = (const float*)d_in[3];
    const float* ln1_b = (const float*)d_in[4];
    const float* w_fc1 = (const float*)d_in[5];
    const float* b_fc1 = (const float*)d_in[6];
    const float* w_fc2 = (const float*)d_in[7];
    const float* b_fc2 = (const float*)d_in[8];
    const float* ln2_g = (const float*)d_in[9];
    const float* ln2_b = (const float*)d_in[10];
    float* out = (float*)d_out;

    float *att, *x1, *mlp;
    __half *qkvh, *ah, *ah2, *b0, *b1, *b2;
    cudaGetSymbolAddress((void**)&att,  g_att);
    cudaGetSymbolAddress((void**)&x1,   g_x1);
    cudaGetSymbolAddress((void**)&mlp,  g_mlp);
    cudaGetSymbolAddress((void**)&qkvh, g_qkvh);
    cudaGetSymbolAddress((void**)&ah,   g_ah);
    cudaGetSymbolAddress((void**)&ah2,  g_ah2);
    cudaGetSymbolAddress((void**)&b0,   g_b0);
    cudaGetSymbolAddress((void**)&b1,   g_b1);
    cudaGetSymbolAddress((void**)&b2,   g_b2);

    cudaFuncSetAttribute((const void*)gemm_mma<1, 2>, cudaFuncAttributeMaxDynamicSharedMemorySize, GM_SMEM2);
    cudaFuncSetAttribute((const void*)gemm_mma<2, 2>, cudaFuncAttributeMaxDynamicSharedMemorySize, GM_SMEM2);
    cudaFuncSetAttribute((const void*)gemm_mma<0, 1>, cudaFuncAttributeMaxDynamicSharedMemorySize, GM_SMEM1);
    cudaFuncSetAttribute((const void*)attn_tc, cudaFuncAttributeMaxDynamicSharedMemorySize, AT_SMEM);

    // ---- all weight transposes + activation round up front ----
    round_w_all<<<11264, 256>>>(w_qkv, b0, w_fc1, b1, w_fc2, b2);
    round_act<<<(M_ * C_ / 4 + 255) / 256, 256>>>(x, ah, (size_t)M_ * C_ / 4);

    // ---- QKV = x @ w_qkv + b  -> fp16 (Q scaled QSCALE) ----
    gemm_mma<1, 2><<<dim3(3 * C_ / 128, M_ / 256), 512, GM_SMEM2>>>(
        ah, b0, b_qkv, nullptr, qkvh, 3 * C_, C_);

    // ---- attention (tensor core, all fp16, 128 q / CTA, 2 CTA/SM) ----
    attn_tc<<<dim3(T_ / 128, H_, B_), 256, AT_SMEM>>>(qkvh, att);

    // ---- x1 = LN1(x + att), fused fp16 round for FC1 A ----
    add_ln_kernel<true><<<M_, 256>>>(x, att, ln1_g, ln1_b, x1, ah);

    // ---- h = gelu(x1 @ w_fc1 + b) -> fp16 ----
    gemm_mma<2, 2><<<dim3(4 * C_ / 128, M_ / 256), 512, GM_SMEM2>>>(
        ah, b1, b_fc1, nullptr, ah2, 4 * C_, C_);

    // ---- mlp = h @ w_fc2 + b (fp32, 128-row tile, 2 CTA/SM) ----
    gemm_mma<0, 1><<<dim3(C_ / 128, M_ / 128), 512, GM_SMEM1>>>(
        ah2, b2, b_fc2, mlp, nullptr, C_, 4 * C_);

    // ---- out = LN2(x1 + mlp) ----
    add_ln_kernel<false><<<M_, 256>>>(x1, mlp, ln2_g, ln2_b, out, nullptr);
}

// round 16
// speedup vs baseline: 1.0594x; 1.0594x over previous
#include <cuda_runtime.h>
#include <cuda_fp16.h>
#include <math.h>
#include <stdint.h>

#define B_   4
#define T_   2048
#define C_   1024
#define H_   16
#define D_   64
#define M_   (B_ * T_)           // 8192 rows
#define LN_EPS 1e-5f
#define QSCALE (0.125f * 1.4426950408889634f)   // 1/sqrt(D) * log2(e)

// ---------------- scratch (static device globals; no allocation) -----------
__device__ __align__(128) float g_att[(size_t)M_ * C_];
__device__ __align__(128) float g_x1 [(size_t)M_ * C_];
__device__ __align__(128) float g_mlp[(size_t)M_ * C_];
__device__ __align__(128) __half g_qkvh[(size_t)M_ * 3 * C_];
__device__ __align__(128) __half g_ah [(size_t)M_ * C_];        // A (x / x1) fp16
__device__ __align__(128) __half g_ah2[(size_t)M_ * 4 * C_];    // gelu(h) fp16
__device__ __align__(128) __half g_b0 [(size_t)3 * C_ * C_];    // w_qkv^T fp16
__device__ __align__(128) __half g_b1 [(size_t)4 * C_ * C_];    // w_fc1^T fp16
__device__ __align__(128) __half g_b2 [(size_t)4 * C_ * C_];    // w_fc2^T fp16

__device__ __forceinline__ float gelu_exact(float x) {
    return 0.5f * x * (1.0f + erff(x * 0.70710678118654752440f));
}

// ---------------- PTX helpers ----------------------------------------------
__device__ __forceinline__ uint32_t smem_u32(const void* p) {
    uint32_t a;
    asm("{ .reg .u64 t; cvta.to.shared.u64 t, %1; cvt.u32.u64 %0, t; }" : "=r"(a) : "l"(p));
    return a;
}
#define CP16(s, g) asm volatile("cp.async.cg.shared.global [%0], [%1], 16;" :: "r"(s), "l"(g))
#define CP_COMMIT() asm volatile("cp.async.commit_group;" ::: "memory")
#define CP_WAIT2()  asm volatile("cp.async.wait_group 2;" ::: "memory")
#define CP_WAIT0()  asm volatile("cp.async.wait_group 0;" ::: "memory")

__device__ __forceinline__ void ldsm4(uint32_t& r0, uint32_t& r1,
                                      uint32_t& r2, uint32_t& r3, uint32_t addr) {
    asm volatile("ldmatrix.sync.aligned.m8n8.x4.shared.b16 {%0,%1,%2,%3}, [%4];"
                 : "=r"(r0), "=r"(r1), "=r"(r2), "=r"(r3) : "r"(addr));
}
__device__ __forceinline__ void ldsm4t(uint32_t& r0, uint32_t& r1,
                                       uint32_t& r2, uint32_t& r3, uint32_t addr) {
    asm volatile("ldmatrix.sync.aligned.m8n8.x4.trans.shared.b16 {%0,%1,%2,%3}, [%4];"
                 : "=r"(r0), "=r"(r1), "=r"(r2), "=r"(r3) : "r"(addr));
}
#define MMA16816(c, a, b)                                                     \
    asm("mma.sync.aligned.m16n8k16.row.col.f32.f16.f16.f32 "                  \
        "{%0,%1,%2,%3}, {%4,%5,%6,%7}, {%8,%9}, {%0,%1,%2,%3};"               \
        : "+f"((c)[0]), "+f"((c)[1]), "+f"((c)[2]), "+f"((c)[3])              \
        : "r"((a)[0]), "r"((a)[1]), "r"((a)[2]), "r"((a)[3]),                 \
          "r"((b)[0]), "r"((b)[1]))

__device__ __forceinline__ uint32_t pack_f16x2(float lo, float hi) {
    uint32_t r;
    asm("cvt.rn.f16x2.f32 %0, %1, %2;" : "=r"(r) : "f"(hi), "f"(lo));
    return r;
}

// ---------------- fused prep: 3 weight transposes + activation round --------
// blocks [0,3072) qkv; [3072,7168) fc1; [7168,11264) fc2; [11264,19456) act.
__global__ void __launch_bounds__(256) prep_all(
    const float* __restrict__ W0, __half* __restrict__ B0,
    const float* __restrict__ W1, __half* __restrict__ B1,
    const float* __restrict__ W2, __half* __restrict__ B2,
    const float* __restrict__ X,  __half* __restrict__ Ah)
{
    int bid = blockIdx.x;
    if (bid >= 11264) {
        size_t i = (size_t)(bid - 11264) * 256 + threadIdx.x;   // < M_*C_/4
        float4 v = ((const float4*)X)[i];
        ((uint32_t*)Ah)[2 * i]     = pack_f16x2(v.x, v.y);
        ((uint32_t*)Ah)[2 * i + 1] = pack_f16x2(v.z, v.w);
        return;
    }
    const float* W; __half* Bh; int K, N;
    if (bid < 3072)      { W = W0; Bh = B0; K = 1024; N = 3072; }
    else if (bid < 7168) { bid -= 3072; W = W1; Bh = B1; K = 1024; N = 4096; }
    else                 { bid -= 7168; W = W2; Bh = B2; K = 4096; N = 1024; }
    const int nbn = N / 32;
    const int n0 = (bid % nbn) * 32, k0 = (bid / nbn) * 32;

    __shared__ float t[32][33];
    const int tx = threadIdx.x & 31, ty = threadIdx.x >> 5;
#pragma unroll
    for (int r = 0; r < 4; r++)
        t[ty + r * 8][tx] = W[(size_t)(k0 + ty + r * 8) * N + n0 + tx];
    __syncthreads();
#pragma unroll
    for (int r = 0; r < 4; r++) {
        int nn = ty + r * 8;
        Bh[(size_t)(n0 + nn) * K + k0 + tx] = __float2half_rn(t[tx][nn]);
    }
}

// ---------------- HMMA fp16 GEMM (fp32 accum, 512 threads) ------------------
// C = A@B^T + bias.  CTA tile 256x128, 16 warps (4m x 4n), warp tile 64x32,
// BK=32, 4 stages.  MODE 0: fp32 out; MODE 1: fp16 out, Q cols scaled QSCALE;
// MODE 2: gelu then fp16 out.
#define GM_BK     32
#define GM_ROWB   80
#define GM_AOP    (256 * GM_ROWB)             // 20480
#define GM_BOP    (128 * GM_ROWB)             // 10240
#define GM_STAGE  (GM_AOP + GM_BOP)           // 30720
#define GM_SMEM   (4 * GM_STAGE)              // 122880

template <int MODE>
__global__ void __launch_bounds__(512, 1) gemm_mma(
    const __half* __restrict__ Ah, const __half* __restrict__ Bh,
    const float* __restrict__ bias, float* __restrict__ Cmat,
    __half* __restrict__ Oh, int N, int K)
{
    extern __shared__ char smem[];
    const uint32_t sb = smem_u32(smem);
    const int tid  = threadIdx.x;
    const int lane = tid & 31;
    const int wid  = tid >> 5;                  // 0..15
    const int m0 = blockIdx.y * 256;
    const int n0 = blockIdx.x * 128;
    const int wm = (wid >> 2) * 64;
    const int wn = (wid & 3) * 32;

    const int nch = K / GM_BK;

    auto load_chunk = [&](int c) {
        const int kk = c * GM_BK;
        const uint32_t st = sb + (c & 3) * GM_STAGE;
#pragma unroll
        for (int i = 0; i < 2; i++) {                // A: 1024 x 16B units
            int u = tid + i * 512;
            int r = u >> 2, cc = u & 3;
            CP16(st + r * GM_ROWB + cc * 16, Ah + (size_t)(m0 + r) * K + kk + cc * 8);
        }
        {                                            // B: 512 x 16B units
            int r = tid >> 2, cc = tid & 3;
            CP16(st + GM_AOP + r * GM_ROWB + cc * 16, Bh + (size_t)(n0 + r) * K + kk + cc * 8);
        }
    };

    float acc[4][4][4];
#pragma unroll
    for (int i = 0; i < 4; i++)
#pragma unroll
        for (int j = 0; j < 4; j++)
#pragma unroll
            for (int t = 0; t < 4; t++) acc[i][j][t] = 0.f;

    load_chunk(0); CP_COMMIT();
    load_chunk(1); CP_COMMIT();
    load_chunk(2); CP_COMMIT();

    const int a_row = lane & 15;
    const int a_off = (lane >> 4) * 16;
    const int b_row = (lane & 7) + ((lane >> 4) << 3);
    const int b_off = ((lane >> 3) & 1) * 16;

    for (int k = 0; k < nch; k++) {
        CP_WAIT2();
        __syncthreads();
        if (k + 3 < nch) load_chunk(k + 3);
        CP_COMMIT();

        const uint32_t stA = sb + (k & 3) * GM_STAGE;
        const uint32_t stB = stA + GM_AOP;

#pragma unroll
        for (int ks = 0; ks < 2; ks++) {
            uint32_t ah[4][4];
#pragma unroll
            for (int mb = 0; mb < 4; mb++) {
                uint32_t ad = stA + (wm + mb * 16 + a_row) * GM_ROWB + ks * 32 + a_off;
                ldsm4(ah[mb][0], ah[mb][1], ah[mb][2], ah[mb][3], ad);
            }
#pragma unroll
            for (int nbp = 0; nbp < 2; nbp++) {
                uint32_t bd = stB + (wn + nbp * 16 + b_row) * GM_ROWB + ks * 32 + b_off;
                uint32_t h0, h1, h2, h3;
                ldsm4(h0, h1, h2, h3, bd);
                uint32_t b0h[2] = {h0, h1}, b1h[2] = {h2, h3};
#pragma unroll
                for (int mb = 0; mb < 4; mb++) MMA16816(acc[mb][2 * nbp],     ah[mb], b0h);
#pragma unroll
                for (int mb = 0; mb < 4; mb++) MMA16816(acc[mb][2 * nbp + 1], ah[mb], b1h);
            }
        }
    }

    // ---- epilogue ----
    const int gr = lane >> 2;
    const int gc = (lane & 3) * 2;
#pragma unroll
    for (int mb = 0; mb < 4; mb++) {
#pragma unroll
        for (int nb = 0; nb < 4; nb++) {
            int row = m0 + wm + mb * 16 + gr;
            int col = n0 + wn + nb * 8 + gc;
            float b0 = __ldg(&bias[col]), b1 = __ldg(&bias[col + 1]);
            float v0 = acc[mb][nb][0] + b0, v1 = acc[mb][nb][1] + b1;
            float v2 = acc[mb][nb][2] + b0, v3 = acc[mb][nb][3] + b1;
            if (MODE == 0) {
                *(float2*)(Cmat + (size_t)row * N + col)       = make_float2(v0, v1);
                *(float2*)(Cmat + (size_t)(row + 8) * N + col) = make_float2(v2, v3);
            } else {
                if (MODE == 1 && col < C_) {
                    v0 *= QSCALE; v1 *= QSCALE; v2 *= QSCALE; v3 *= QSCALE;
                }
                if (MODE == 2) {
                    v0 = gelu_exact(v0); v1 = gelu_exact(v1);
                    v2 = gelu_exact(v2); v3 = gelu_exact(v3);
                }
                *(uint32_t*)(Oh + (size_t)row * N + col)       = pack_f16x2(v0, v1);
                *(uint32_t*)(Oh + (size_t)(row + 8) * N + col) = pack_f16x2(v2, v3);
            }
        }
    }
}

// ---------------- tensor-core causal flash attention (all fp16) -------------
#define AT_ROWB  144
#define AQ_T     (128 * AT_ROWB)             // 18432 (Q)
#define AK_T     (64 * AT_ROWB)              // 9216 per K/V operand
#define AT_STAGE (2 * AK_T)                  // Kh,Vh = 18432
#define AT_SMEM  (AQ_T + 2 * AT_STAGE)       // 55296

__global__ void __launch_bounds__(256, 2) attn_tc(
    const __half* __restrict__ qkvh, float* __restrict__ y)
{
    extern __shared__ char smem[];
    const uint32_t sb = smem_u32(smem);
    const int tid = threadIdx.x, lane = tid & 31, wid = tid >> 5;
    const int qb = (int)gridDim.x - 1 - (int)blockIdx.x;
    const int h = blockIdx.y, b = blockIdx.z;
    const int q0 = qb * 128;
    const int wq = wid * 16;
    const int gr = lane >> 2, gc = lane & 3;
    const int RS = 3 * C_;

    const __half* qh = qkvh + (size_t)b * T_ * RS + h * D_;
    const __half* kh = qh + C_;
    const __half* vh = qh + 2 * C_;

    const uint32_t QH  = sb;
    const uint32_t ST0 = sb + AQ_T;

#pragma unroll
    for (int i = 0; i < 4; i++) {
        int u = tid + i * 256;
        int r = u >> 3, c = u & 7;
        CP16(QH + r * AT_ROWB + c * 16, qh + (size_t)(q0 + r) * RS + c * 8);
    }

    auto load_tile = [&](int kt, int bufsel) {
        uint32_t st = ST0 + bufsel * AT_STAGE;
#pragma unroll
        for (int t = 0; t < 2; t++) {
            const __half* g = (t == 0 ? kh : vh);
#pragma unroll
            for (int i = 0; i < 2; i++) {
                int u = tid + i * 256;
                int r = u >> 3, c = u & 7;
                CP16(st + t * AK_T + r * AT_ROWB + c * 16, g + (size_t)(kt * 64 + r) * RS + c * 8);
            }
        }
    };
    load_tile(0, 0);
    CP_COMMIT();
    CP_WAIT0();
    __syncthreads();

    uint32_t qf[4][4];
    const int a_row = lane & 15, a_off = (lane >> 4) * 16;
#pragma unroll
    for (int ks = 0; ks < 4; ks++) {
        uint32_t ad = QH + (wq + a_row) * AT_ROWB + ks * 32 + a_off;
        ldsm4(qf[ks][0], qf[ks][1], qf[ks][2], qf[ks][3], ad);
    }

    float Oacc[8][4];
#pragma unroll
    for (int i = 0; i < 8; i++)
#pragma unroll
        for (int j = 0; j < 4; j++) Oacc[i][j] = 0.f;
    float m0 = -1e30f, m1 = -1e30f, l0 = 0.f, l1 = 0.f;

    const int nt = 2 * qb + 2;
    const int b_row = (lane & 7) + ((lane >> 4) << 3);
    const int b_off = ((lane >> 3) & 1) * 16;
    const int v_row = (lane & 7) + ((lane >> 3) & 1) * 8;
    const int v_off = (lane >> 4) * 16;

    for (int kt = 0; kt < nt; kt++) {
        if (kt + 1 < nt) { load_tile(kt + 1, (kt + 1) & 1); CP_COMMIT(); }
        const uint32_t st = ST0 + (kt & 1) * AT_STAGE;

        const bool active = (kt * 64) <= (q0 + wq + 15);
        if (active) {
            float sacc[8][4];
#pragma unroll
            for (int i = 0; i < 8; i++)
#pragma unroll
                for (int j = 0; j < 4; j++) sacc[i][j] = 0.f;

#pragma unroll
            for (int nbp = 0; nbp < 4; nbp++) {
#pragma unroll
                for (int ks = 0; ks < 4; ks++) {
                    uint32_t kd = st + (nbp * 16 + b_row) * AT_ROWB + ks * 32 + b_off;
                    uint32_t r0, r1, r2, r3;
                    ldsm4(r0, r1, r2, r3, kd);
                    uint32_t b0[2] = {r0, r1}, b1[2] = {r2, r3};
                    MMA16816(sacc[2 * nbp],     qf[ks], b0);
                    MMA16816(sacc[2 * nbp + 1], qf[ks], b1);
                }
            }

            if (kt * 64 + 63 > q0 + wq) {
                const int qg0 = q0 + wq + gr, qg1 = qg0 + 8;
#pragma unroll
                for (int nb = 0; nb < 8; nb++) {
                    int kg = kt * 64 + nb * 8 + 2 * gc;
                    if (kg     > qg0) sacc[nb][0] = -1e30f;
                    if (kg + 1 > qg0) sacc[nb][1] = -1e30f;
                    if (kg     > qg1) sacc[nb][2] = -1e30f;
                    if (kg + 1 > qg1) sacc[nb][3] = -1e30f;
                }
            }

            float mx0 = m0, mx1 = m1;
#pragma unroll
            for (int nb = 0; nb < 8; nb++) {
                mx0 = fmaxf(mx0, fmaxf(sacc[nb][0], sacc[nb][1]));
                mx1 = fmaxf(mx1, fmaxf(sacc[nb][2], sacc[nb][3]));
            }
            mx0 = fmaxf(mx0, __shfl_xor_sync(0xffffffffu, mx0, 1));
            mx0 = fmaxf(mx0, __shfl_xor_sync(0xffffffffu, mx0, 2));
            mx1 = fmaxf(mx1, __shfl_xor_sync(0xffffffffu, mx1, 1));
            mx1 = fmaxf(mx1, __shfl_xor_sync(0xffffffffu, mx1, 2));
            float al0 = exp2f(m0 - mx0), al1 = exp2f(m1 - mx1);
            m0 = mx0; m1 = mx1;
            float ls0 = 0.f, ls1 = 0.f;
#pragma unroll
            for (int nb = 0; nb < 8; nb++) {
                sacc[nb][0] = exp2f(sacc[nb][0] - mx0); ls0 += sacc[nb][0];
                sacc[nb][1] = exp2f(sacc[nb][1] - mx0); ls0 += sacc[nb][1];
                sacc[nb][2] = exp2f(sacc[nb][2] - mx1); ls1 += sacc[nb][2];
                sacc[nb][3] = exp2f(sacc[nb][3] - mx1); ls1 += sacc[nb][3];
            }
            l0 = l0 * al0 + ls0;
            l1 = l1 * al1 + ls1;
#pragma unroll
            for (int nb = 0; nb < 8; nb++) {
                Oacc[nb][0] *= al0; Oacc[nb][1] *= al0;
                Oacc[nb][2] *= al1; Oacc[nb][3] *= al1;
            }

#pragma unroll
            for (int kb = 0; kb < 4; kb++) {
                uint32_t ph[4];
                ph[0] = pack_f16x2(sacc[2 * kb][0],     sacc[2 * kb][1]);
                ph[1] = pack_f16x2(sacc[2 * kb][2],     sacc[2 * kb][3]);
                ph[2] = pack_f16x2(sacc[2 * kb + 1][0], sacc[2 * kb + 1][1]);
                ph[3] = pack_f16x2(sacc[2 * kb + 1][2], sacc[2 * kb + 1][3]);
#pragma unroll
                for (int nbp = 0; nbp < 4; nbp++) {
                    uint32_t vd = st + AK_T + (kb * 16 + v_row) * AT_ROWB + nbp * 32 + v_off;
                    uint32_t r0, r1, r2, r3;
                    ldsm4t(r0, r1, r2, r3, vd);
                    uint32_t v0[2] = {r0, r1}, v1[2] = {r2, r3};
                    MMA16816(Oacc[2 * nbp],     ph, v0);
                    MMA16816(Oacc[2 * nbp + 1], ph, v1);
                }
            }
        }

        CP_WAIT0();
        __syncthreads();
    }

    l0 += __shfl_xor_sync(0xffffffffu, l0, 1);
    l0 += __shfl_xor_sync(0xffffffffu, l0, 2);
    l1 += __shfl_xor_sync(0xffffffffu, l1, 1);
    l1 += __shfl_xor_sync(0xffffffffu, l1, 2);
    const float inv0 = 1.f / l0, inv1 = 1.f / l1;

    float* yb = y + ((size_t)b * T_ + q0 + wq) * C_ + h * D_;
#pragma unroll
    for (int nb = 0; nb < 8; nb++) {
        int col = nb * 8 + 2 * gc;
        *(float2*)(yb + (size_t)gr * C_ + col) =
            make_float2(Oacc[nb][0] * inv0, Oacc[nb][1] * inv0);
        *(float2*)(yb + (size_t)(gr + 8) * C_ + col) =
            make_float2(Oacc[nb][2] * inv1, Oacc[nb][3] * inv1);
    }
}

// ---------------- residual add + LayerNorm (+ optional fp16 out) -----------
template <bool SPLIT>
__global__ void __launch_bounds__(256) add_ln_kernel(
    const float* __restrict__ a, const float* __restrict__ bres,
    const float* __restrict__ g, const float* __restrict__ beta,
    float* __restrict__ out, __half* __restrict__ Oh)
{
    const int row = blockIdx.x;
    const int tid = threadIdx.x;

    const float4 av = ((const float4*)(a    + (size_t)row * C_))[tid];
    const float4 bv = ((const float4*)(bres + (size_t)row * C_))[tid];
    float4 v = make_float4(av.x + bv.x, av.y + bv.y, av.z + bv.z, av.w + bv.w);

    float s  = v.x + v.y + v.z + v.w;
    float sq = v.x * v.x + v.y * v.y + v.z * v.z + v.w * v.w;
#pragma unroll
    for (int off = 16; off; off >>= 1) {
        s  += __shfl_xor_sync(0xffffffffu, s,  off);
        sq += __shfl_xor_sync(0xffffffffu, sq, off);
    }
    __shared__ float ws[8], wsq[8];
    if ((tid & 31) == 0) { ws[tid >> 5] = s; wsq[tid >> 5] = sq; }
    __syncthreads();
    float tot = 0.f, totq = 0.f;
#pragma unroll
    for (int i = 0; i < 8; i++) { tot += ws[i]; totq += wsq[i]; }

    const float mu   = tot * (1.0f / C_);
    const float var  = totq * (1.0f / C_) - mu * mu;
    const float rstd = rsqrtf(var + LN_EPS);

    const float4 gv = ((const float4*)g)[tid];
    const float4 be = ((const float4*)beta)[tid];
    float4 o;
    o.x = (v.x - mu) * rstd * gv.x + be.x;
    o.y = (v.y - mu) * rstd * gv.y + be.y;
    o.z = (v.z - mu) * rstd * gv.z + be.z;
    o.w = (v.w - mu) * rstd * gv.w + be.w;
    ((float4*)(out + (size_t)row * C_))[tid] = o;
    if (SPLIT) {
        uint32_t* oh = (uint32_t*)(Oh + (size_t)row * C_);
        oh[2 * tid]     = pack_f16x2(o.x, o.y);
        oh[2 * tid + 1] = pack_f16x2(o.z, o.w);
    }
}

// ---------------- launcher --------------------------------------------------
extern "C" void kernel_launch(void* const* d_in, const int* in_sizes, int n_in,
                              void* d_out, int out_size)
{
    const float* x     = (const float*)d_in[0];
    const float* w_qkv = (const float*)d_in[1];
    const float* b_qkv = (const float*)d_in[2];
    const float* ln1_g = (const float*)d_in[3];
    const float* ln1_b = (const float*)d_in[4];
    const float* w_fc1 = (const float*)d_in[5];
    const float* b_fc1 = (const float*)d_in[6];
    const float* w_fc2 = (const float*)d_in[7];
    const float* b_fc2 = (const float*)d_in[8];
    const float* ln2_g = (const float*)d_in[9];
    const float* ln2_b = (const float*)d_in[10];
    float* out = (float*)d_out;

    float *att, *x1, *mlp;
    __half *qkvh, *ah, *ah2, *b0, *b1, *b2;
    cudaGetSymbolAddress((void**)&att,  g_att);
    cudaGetSymbolAddress((void**)&x1,   g_x1);
    cudaGetSymbolAddress((void**)&mlp,  g_mlp);
    cudaGetSymbolAddress((void**)&qkvh, g_qkvh);
    cudaGetSymbolAddress((void**)&ah,   g_ah);
    cudaGetSymbolAddress((void**)&ah2,  g_ah2);
    cudaGetSymbolAddress((void**)&b0,   g_b0);
    cudaGetSymbolAddress((void**)&b1,   g_b1);
    cudaGetSymbolAddress((void**)&b2,   g_b2);

    cudaFuncSetAttribute(gemm_mma<0>, cudaFuncAttributeMaxDynamicSharedMemorySize, GM_SMEM);
    cudaFuncSetAttribute(gemm_mma<1>, cudaFuncAttributeMaxDynamicSharedMemorySize, GM_SMEM);
    cudaFuncSetAttribute(gemm_mma<2>, cudaFuncAttributeMaxDynamicSharedMemorySize, GM_SMEM);
    cudaFuncSetAttribute(attn_tc, cudaFuncAttributeMaxDynamicSharedMemorySize, AT_SMEM);

    // ---- fused prep: all weight transposes + activation round ----
    prep_all<<<11264 + M_ * C_ / 4 / 256, 256>>>(w_qkv, b0, w_fc1, b1, w_fc2, b2, x, ah);

    // ---- QKV = x @ w_qkv + b  -> fp16 (Q scaled QSCALE) ----
    gemm_mma<1><<<dim3(3 * C_ / 128, M_ / 256), 512, GM_SMEM>>>(
        ah, b0, b_qkv, nullptr, qkvh, 3 * C_, C_);

    // ---- attention (tensor core, all fp16, 128 q / CTA, 2 CTA/SM) ----
    attn_tc<<<dim3(T_ / 128, H_, B_), 256, AT_SMEM>>>(qkvh, att);

    // ---- x1 = LN1(x + att), fused fp16 round for FC1 A ----
    add_ln_kernel<true><<<M_, 256>>>(x, att, ln1_g, ln1_b, x1, ah);

    // ---- h = gelu(x1 @ w_fc1 + b) -> fp16 ----
    gemm_mma<2><<<dim3(4 * C_ / 128, M_ / 256), 512, GM_SMEM>>>(
        ah, b1, b_fc1, nullptr, ah2, 4 * C_, C_);

    // ---- mlp = h @ w_fc2 + b (fp32) ----
    gemm_mma<0><<<dim3(C_ / 128, M_ / 256), 512, GM_SMEM>>>(
        ah2, b2, b_fc2, mlp, nullptr, C_, 4 * C_);

    // ---- out = LN2(x1 + mlp) ----
    add_ln_kernel<false><<<M_, 256>>>(x1, mlp, ln2_g, ln2_b, out, nullptr);
}

// round 17
// speedup vs baseline: 1.0604x; 1.0009x over previous
#include <cuda_runtime.h>
#include <cuda_fp16.h>
#include <math.h>
#include <stdint.h>

#define B_   4
#define T_   2048
#define C_   1024
#define H_   16
#define D_   64
#define M_   (B_ * T_)           // 8192 rows
#define LN_EPS 1e-5f
#define QSCALE (0.125f * 1.4426950408889634f)   // 1/sqrt(D) * log2(e)

// ---------------- scratch (static device globals; no allocation) -----------
__device__ __align__(128) float g_x1 [(size_t)M_ * C_];
__device__ __align__(128) float g_mlp[(size_t)M_ * C_];
__device__ __align__(128) __half g_qkvh[(size_t)M_ * 3 * C_];
__device__ __align__(128) __half g_ah [(size_t)M_ * C_];        // A (x / x1) fp16
__device__ __align__(128) __half g_ah2[(size_t)M_ * 4 * C_];    // att fp16, then gelu(h) fp16
__device__ __align__(128) __half g_b0 [(size_t)3 * C_ * C_];    // w_qkv^T fp16
__device__ __align__(128) __half g_b1 [(size_t)4 * C_ * C_];    // w_fc1^T fp16
__device__ __align__(128) __half g_b2 [(size_t)4 * C_ * C_];    // w_fc2^T fp16

__device__ __forceinline__ float gelu_exact(float x) {
    return 0.5f * x * (1.0f + erff(x * 0.70710678118654752440f));
}

// ---------------- PTX helpers ----------------------------------------------
__device__ __forceinline__ uint32_t smem_u32(const void* p) {
    uint32_t a;
    asm("{ .reg .u64 t; cvta.to.shared.u64 t, %1; cvt.u32.u64 %0, t; }" : "=r"(a) : "l"(p));
    return a;
}
#define CP16(s, g) asm volatile("cp.async.cg.shared.global [%0], [%1], 16;" :: "r"(s), "l"(g))
#define CP_COMMIT() asm volatile("cp.async.commit_group;" ::: "memory")
#define CP_WAIT2()  asm volatile("cp.async.wait_group 2;" ::: "memory")
#define CP_WAIT0()  asm volatile("cp.async.wait_group 0;" ::: "memory")

__device__ __forceinline__ void ldsm4(uint32_t& r0, uint32_t& r1,
                                      uint32_t& r2, uint32_t& r3, uint32_t addr) {
    asm volatile("ldmatrix.sync.aligned.m8n8.x4.shared.b16 {%0,%1,%2,%3}, [%4];"
                 : "=r"(r0), "=r"(r1), "=r"(r2), "=r"(r3) : "r"(addr));
}
__device__ __forceinline__ void ldsm4t(uint32_t& r0, uint32_t& r1,
                                       uint32_t& r2, uint32_t& r3, uint32_t addr) {
    asm volatile("ldmatrix.sync.aligned.m8n8.x4.trans.shared.b16 {%0,%1,%2,%3}, [%4];"
                 : "=r"(r0), "=r"(r1), "=r"(r2), "=r"(r3) : "r"(addr));
}
#define MMA16816(c, a, b)                                                     \
    asm("mma.sync.aligned.m16n8k16.row.col.f32.f16.f16.f32 "                  \
        "{%0,%1,%2,%3}, {%4,%5,%6,%7}, {%8,%9}, {%0,%1,%2,%3};"               \
        : "+f"((c)[0]), "+f"((c)[1]), "+f"((c)[2]), "+f"((c)[3])              \
        : "r"((a)[0]), "r"((a)[1]), "r"((a)[2]), "r"((a)[3]),                 \
          "r"((b)[0]), "r"((b)[1]))

__device__ __forceinline__ uint32_t pack_f16x2(float lo, float hi) {
    uint32_t r;
    asm("cvt.rn.f16x2.f32 %0, %1, %2;" : "=r"(r) : "f"(hi), "f"(lo));
    return r;
}

// ---------------- fused prep: 3 weight transposes + activation round --------
// blocks [0,3072) qkv; [3072,7168) fc1; [7168,11264) fc2; [11264,19456) act.
__global__ void __launch_bounds__(256) prep_all(
    const float* __restrict__ W0, __half* __restrict__ B0,
    const float* __restrict__ W1, __half* __restrict__ B1,
    const float* __restrict__ W2, __half* __restrict__ B2,
    const float* __restrict__ X,  __half* __restrict__ Ah)
{
    int bid = blockIdx.x;
    if (bid >= 11264) {
        size_t i = (size_t)(bid - 11264) * 256 + threadIdx.x;   // < M_*C_/4
        float4 v = ((const float4*)X)[i];
        ((uint32_t*)Ah)[2 * i]     = pack_f16x2(v.x, v.y);
        ((uint32_t*)Ah)[2 * i + 1] = pack_f16x2(v.z, v.w);
        return;
    }
    const float* W; __half* Bh; int K, N;
    if (bid < 3072)      { W = W0; Bh = B0; K = 1024; N = 3072; }
    else if (bid < 7168) { bid -= 3072; W = W1; Bh = B1; K = 1024; N = 4096; }
    else                 { bid -= 7168; W = W2; Bh = B2; K = 4096; N = 1024; }
    const int nbn = N / 32;
    const int n0 = (bid % nbn) * 32, k0 = (bid / nbn) * 32;

    __shared__ float t[32][33];
    const int tx = threadIdx.x & 31, ty = threadIdx.x >> 5;
#pragma unroll
    for (int r = 0; r < 4; r++)
        t[ty + r * 8][tx] = W[(size_t)(k0 + ty + r * 8) * N + n0 + tx];
    __syncthreads();
#pragma unroll
    for (int r = 0; r < 4; r++) {
        int nn = ty + r * 8;
        Bh[(size_t)(n0 + nn) * K + k0 + tx] = __float2half_rn(t[tx][nn]);
    }
}

// ---------------- HMMA fp16 GEMM (fp32 accum, 512 threads) ------------------
// C = A@B^T + bias.  CTA tile 256x128, 16 warps (4m x 4n), warp tile 64x32,
// BK=32, 4 stages.  MODE 0: fp32 out; MODE 1: fp16 out, Q cols scaled QSCALE;
// MODE 2: gelu then fp16 out.
#define GM_BK     32
#define GM_ROWB   80
#define GM_AOP    (256 * GM_ROWB)             // 20480
#define GM_BOP    (128 * GM_ROWB)             // 10240
#define GM_STAGE  (GM_AOP + GM_BOP)           // 30720
#define GM_SMEM   (4 * GM_STAGE)              // 122880

template <int MODE>
__global__ void __launch_bounds__(512, 1) gemm_mma(
    const __half* __restrict__ Ah, const __half* __restrict__ Bh,
    const float* __restrict__ bias, float* __restrict__ Cmat,
    __half* __restrict__ Oh, int N, int K)
{
    extern __shared__ char smem[];
    const uint32_t sb = smem_u32(smem);
    const int tid  = threadIdx.x;
    const int lane = tid & 31;
    const int wid  = tid >> 5;                  // 0..15
    const int m0 = blockIdx.y * 256;
    const int n0 = blockIdx.x * 128;
    const int wm = (wid >> 2) * 64;
    const int wn = (wid & 3) * 32;

    const int nch = K / GM_BK;

    auto load_chunk = [&](int c) {
        const int kk = c * GM_BK;
        const uint32_t st = sb + (c & 3) * GM_STAGE;
#pragma unroll
        for (int i = 0; i < 2; i++) {                // A: 1024 x 16B units
            int u = tid + i * 512;
            int r = u >> 2, cc = u & 3;
            CP16(st + r * GM_ROWB + cc * 16, Ah + (size_t)(m0 + r) * K + kk + cc * 8);
        }
        {                                            // B: 512 x 16B units
            int r = tid >> 2, cc = tid & 3;
            CP16(st + GM_AOP + r * GM_ROWB + cc * 16, Bh + (size_t)(n0 + r) * K + kk + cc * 8);
        }
    };

    float acc[4][4][4];
#pragma unroll
    for (int i = 0; i < 4; i++)
#pragma unroll
        for (int j = 0; j < 4; j++)
#pragma unroll
            for (int t = 0; t < 4; t++) acc[i][j][t] = 0.f;

    load_chunk(0); CP_COMMIT();
    load_chunk(1); CP_COMMIT();
    load_chunk(2); CP_COMMIT();

    const int a_row = lane & 15;
    const int a_off = (lane >> 4) * 16;
    const int b_row = (lane & 7) + ((lane >> 4) << 3);
    const int b_off = ((lane >> 3) & 1) * 16;

    for (int k = 0; k < nch; k++) {
        CP_WAIT2();
        __syncthreads();
        if (k + 3 < nch) load_chunk(k + 3);
        CP_COMMIT();

        const uint32_t stA = sb + (k & 3) * GM_STAGE;
        const uint32_t stB = stA + GM_AOP;

#pragma unroll
        for (int ks = 0; ks < 2; ks++) {
            uint32_t ah[4][4];
#pragma unroll
            for (int mb = 0; mb < 4; mb++) {
                uint32_t ad = stA + (wm + mb * 16 + a_row) * GM_ROWB + ks * 32 + a_off;
                ldsm4(ah[mb][0], ah[mb][1], ah[mb][2], ah[mb][3], ad);
            }
#pragma unroll
            for (int nbp = 0; nbp < 2; nbp++) {
                uint32_t bd = stB + (wn + nbp * 16 + b_row) * GM_ROWB + ks * 32 + b_off;
                uint32_t h0, h1, h2, h3;
                ldsm4(h0, h1, h2, h3, bd);
                uint32_t b0h[2] = {h0, h1}, b1h[2] = {h2, h3};
#pragma unroll
                for (int mb = 0; mb < 4; mb++) MMA16816(acc[mb][2 * nbp],     ah[mb], b0h);
#pragma unroll
                for (int mb = 0; mb < 4; mb++) MMA16816(acc[mb][2 * nbp + 1], ah[mb], b1h);
            }
        }
    }

    // ---- epilogue ----
    const int gr = lane >> 2;
    const int gc = (lane & 3) * 2;
#pragma unroll
    for (int mb = 0; mb < 4; mb++) {
#pragma unroll
        for (int nb = 0; nb < 4; nb++) {
            int row = m0 + wm + mb * 16 + gr;
            int col = n0 + wn + nb * 8 + gc;
            float b0 = __ldg(&bias[col]), b1 = __ldg(&bias[col + 1]);
            float v0 = acc[mb][nb][0] + b0, v1 = acc[mb][nb][1] + b1;
            float v2 = acc[mb][nb][2] + b0, v3 = acc[mb][nb][3] + b1;
            if (MODE == 0) {
                *(float2*)(Cmat + (size_t)row * N + col)       = make_float2(v0, v1);
                *(float2*)(Cmat + (size_t)(row + 8) * N + col) = make_float2(v2, v3);
            } else {
                if (MODE == 1 && col < C_) {
                    v0 *= QSCALE; v1 *= QSCALE; v2 *= QSCALE; v3 *= QSCALE;
                }
                if (MODE == 2) {
                    v0 = gelu_exact(v0); v1 = gelu_exact(v1);
                    v2 = gelu_exact(v2); v3 = gelu_exact(v3);
                }
                *(uint32_t*)(Oh + (size_t)row * N + col)       = pack_f16x2(v0, v1);
                *(uint32_t*)(Oh + (size_t)(row + 8) * N + col) = pack_f16x2(v2, v3);
            }
        }
    }
}

// ---------------- tensor-core causal flash attention (all fp16) -------------
#define AT_ROWB  144
#define AQ_T     (128 * AT_ROWB)             // 18432 (Q)
#define AK_T     (64 * AT_ROWB)              // 9216 per K/V operand
#define AT_STAGE (2 * AK_T)                  // Kh,Vh = 18432
#define AT_SMEM  (AQ_T + 2 * AT_STAGE)       // 55296

__global__ void __launch_bounds__(256, 2) attn_tc(
    const __half* __restrict__ qkvh, __half* __restrict__ y)
{
    extern __shared__ char smem[];
    const uint32_t sb = smem_u32(smem);
    const int tid = threadIdx.x, lane = tid & 31, wid = tid >> 5;
    const int qb = (int)gridDim.x - 1 - (int)blockIdx.x;
    const int h = blockIdx.y, b = blockIdx.z;
    const int q0 = qb * 128;
    const int wq = wid * 16;
    const int gr = lane >> 2, gc = lane & 3;
    const int RS = 3 * C_;

    const __half* qh = qkvh + (size_t)b * T_ * RS + h * D_;
    const __half* kh = qh + C_;
    const __half* vh = qh + 2 * C_;

    const uint32_t QH  = sb;
    const uint32_t ST0 = sb + AQ_T;

#pragma unroll
    for (int i = 0; i < 4; i++) {
        int u = tid + i * 256;
        int r = u >> 3, c = u & 7;
        CP16(QH + r * AT_ROWB + c * 16, qh + (size_t)(q0 + r) * RS + c * 8);
    }

    auto load_tile = [&](int kt, int bufsel) {
        uint32_t st = ST0 + bufsel * AT_STAGE;
#pragma unroll
        for (int t = 0; t < 2; t++) {
            const __half* g = (t == 0 ? kh : vh);
#pragma unroll
            for (int i = 0; i < 2; i++) {
                int u = tid + i * 256;
                int r = u >> 3, c = u & 7;
                CP16(st + t * AK_T + r * AT_ROWB + c * 16, g + (size_t)(kt * 64 + r) * RS + c * 8);
            }
        }
    };
    load_tile(0, 0);
    CP_COMMIT();
    CP_WAIT0();
    __syncthreads();

    uint32_t qf[4][4];
    const int a_row = lane & 15, a_off = (lane >> 4) * 16;
#pragma unroll
    for (int ks = 0; ks < 4; ks++) {
        uint32_t ad = QH + (wq + a_row) * AT_ROWB + ks * 32 + a_off;
        ldsm4(qf[ks][0], qf[ks][1], qf[ks][2], qf[ks][3], ad);
    }

    float Oacc[8][4];
#pragma unroll
    for (int i = 0; i < 8; i++)
#pragma unroll
        for (int j = 0; j < 4; j++) Oacc[i][j] = 0.f;
    float m0 = -1e30f, m1 = -1e30f, l0 = 0.f, l1 = 0.f;

    const int nt = 2 * qb + 2;
    const int b_row = (lane & 7) + ((lane >> 4) << 3);
    const int b_off = ((lane >> 3) & 1) * 16;
    const int v_row = (lane & 7) + ((lane >> 3) & 1) * 8;
    const int v_off = (lane >> 4) * 16;

    for (int kt = 0; kt < nt; kt++) {
        if (kt + 1 < nt) { load_tile(kt + 1, (kt + 1) & 1); CP_COMMIT(); }
        const uint32_t st = ST0 + (kt & 1) * AT_STAGE;

        const bool active = (kt * 64) <= (q0 + wq + 15);
        if (active) {
            float sacc[8][4];
#pragma unroll
            for (int i = 0; i < 8; i++)
#pragma unroll
                for (int j = 0; j < 4; j++) sacc[i][j] = 0.f;

#pragma unroll
            for (int nbp = 0; nbp < 4; nbp++) {
#pragma unroll
                for (int ks = 0; ks < 4; ks++) {
                    uint32_t kd = st + (nbp * 16 + b_row) * AT_ROWB + ks * 32 + b_off;
                    uint32_t r0, r1, r2, r3;
                    ldsm4(r0, r1, r2, r3, kd);
                    uint32_t b0[2] = {r0, r1}, b1[2] = {r2, r3};
                    MMA16816(sacc[2 * nbp],     qf[ks], b0);
                    MMA16816(sacc[2 * nbp + 1], qf[ks], b1);
                }
            }

            if (kt * 64 + 63 > q0 + wq) {
                const int qg0 = q0 + wq + gr, qg1 = qg0 + 8;
#pragma unroll
                for (int nb = 0; nb < 8; nb++) {
                    int kg = kt * 64 + nb * 8 + 2 * gc;
                    if (kg     > qg0) sacc[nb][0] = -1e30f;
                    if (kg + 1 > qg0) sacc[nb][1] = -1e30f;
                    if (kg     > qg1) sacc[nb][2] = -1e30f;
                    if (kg + 1 > qg1) sacc[nb][3] = -1e30f;
                }
            }

            float mx0 = m0, mx1 = m1;
#pragma unroll
            for (int nb = 0; nb < 8; nb++) {
                mx0 = fmaxf(mx0, fmaxf(sacc[nb][0], sacc[nb][1]));
                mx1 = fmaxf(mx1, fmaxf(sacc[nb][2], sacc[nb][3]));
            }
            mx0 = fmaxf(mx0, __shfl_xor_sync(0xffffffffu, mx0, 1));
            mx0 = fmaxf(mx0, __shfl_xor_sync(0xffffffffu, mx0, 2));
            mx1 = fmaxf(mx1, __shfl_xor_sync(0xffffffffu, mx1, 1));
            mx1 = fmaxf(mx1, __shfl_xor_sync(0xffffffffu, mx1, 2));
            float al0 = exp2f(m0 - mx0), al1 = exp2f(m1 - mx1);
            m0 = mx0; m1 = mx1;
            float ls0 = 0.f, ls1 = 0.f;
#pragma unroll
            for (int nb = 0; nb < 8; nb++) {
                sacc[nb][0] = exp2f(sacc[nb][0] - mx0); ls0 += sacc[nb][0];
                sacc[nb][1] = exp2f(sacc[nb][1] - mx0); ls0 += sacc[nb][1];
                sacc[nb][2] = exp2f(sacc[nb][2] - mx1); ls1 += sacc[nb][2];
                sacc[nb][3] = exp2f(sacc[nb][3] - mx1); ls1 += sacc[nb][3];
            }
            l0 = l0 * al0 + ls0;
            l1 = l1 * al1 + ls1;
#pragma unroll
            for (int nb = 0; nb < 8; nb++) {
                Oacc[nb][0] *= al0; Oacc[nb][1] *= al0;
                Oacc[nb][2] *= al1; Oacc[nb][3] *= al1;
            }

#pragma unroll
            for (int kb = 0; kb < 4; kb++) {
                uint32_t ph[4];
                ph[0] = pack_f16x2(sacc[2 * kb][0],     sacc[2 * kb][1]);
                ph[1] = pack_f16x2(sacc[2 * kb][2],     sacc[2 * kb][3]);
                ph[2] = pack_f16x2(sacc[2 * kb + 1][0], sacc[2 * kb + 1][1]);
                ph[3] = pack_f16x2(sacc[2 * kb + 1][2], sacc[2 * kb + 1][3]);
#pragma unroll
                for (int nbp = 0; nbp < 4; nbp++) {
                    uint32_t vd = st + AK_T + (kb * 16 + v_row) * AT_ROWB + nbp * 32 + v_off;
                    uint32_t r0, r1, r2, r3;
                    ldsm4t(r0, r1, r2, r3, vd);
                    uint32_t v0[2] = {r0, r1}, v1[2] = {r2, r3};
                    MMA16816(Oacc[2 * nbp],     ph, v0);
                    MMA16816(Oacc[2 * nbp + 1], ph, v1);
                }
            }
        }

        CP_WAIT0();
        __syncthreads();
    }

    l0 += __shfl_xor_sync(0xffffffffu, l0, 1);
    l0 += __shfl_xor_sync(0xffffffffu, l0, 2);
    l1 += __shfl_xor_sync(0xffffffffu, l1, 1);
    l1 += __shfl_xor_sync(0xffffffffu, l1, 2);
    const float inv0 = 1.f / l0, inv1 = 1.f / l1;

    // write att as fp16 (consumed by LN1; values O(1))
    __half* yb = y + ((size_t)b * T_ + q0 + wq) * C_ + h * D_;
#pragma unroll
    for (int nb = 0; nb < 8; nb++) {
        int col = nb * 8 + 2 * gc;
        *(uint32_t*)(yb + (size_t)gr * C_ + col) =
            pack_f16x2(Oacc[nb][0] * inv0, Oacc[nb][1] * inv0);
        *(uint32_t*)(yb + (size_t)(gr + 8) * C_ + col) =
            pack_f16x2(Oacc[nb][2] * inv1, Oacc[nb][3] * inv1);
    }
}

// ---------------- residual add + LayerNorm (+ optional fp16 out) -----------
// HALF_B: residual addend (bres) is fp16 (attention output path).
template <bool SPLIT, bool HALF_B>
__global__ void __launch_bounds__(256) add_ln_kernel(
    const float* __restrict__ a, const void* __restrict__ bres,
    const float* __restrict__ g, const float* __restrict__ beta,
    float* __restrict__ out, __half* __restrict__ Oh)
{
    const int row = blockIdx.x;
    const int tid = threadIdx.x;

    const float4 av = ((const float4*)(a + (size_t)row * C_))[tid];
    float4 bv;
    if (HALF_B) {
        const uint32_t* bp = (const uint32_t*)((const __half*)bres + (size_t)row * C_);
        float2 p0 = __half22float2(*(const __half2*)&bp[2 * tid]);
        float2 p1 = __half22float2(*(const __half2*)&bp[2 * tid + 1]);
        bv = make_float4(p0.x, p0.y, p1.x, p1.y);
    } else {
        bv = ((const float4*)((const float*)bres + (size_t)row * C_))[tid];
    }
    float4 v = make_float4(av.x + bv.x, av.y + bv.y, av.z + bv.z, av.w + bv.w);

    float s  = v.x + v.y + v.z + v.w;
    float sq = v.x * v.x + v.y * v.y + v.z * v.z + v.w * v.w;
#pragma unroll
    for (int off = 16; off; off >>= 1) {
        s  += __shfl_xor_sync(0xffffffffu, s,  off);
        sq += __shfl_xor_sync(0xffffffffu, sq, off);
    }
    __shared__ float ws[8], wsq[8];
    if ((tid & 31) == 0) { ws[tid >> 5] = s; wsq[tid >> 5] = sq; }
    __syncthreads();
    float tot = 0.f, totq = 0.f;
#pragma unroll
    for (int i = 0; i < 8; i++) { tot += ws[i]; totq += wsq[i]; }

    const float mu   = tot * (1.0f / C_);
    const float var  = totq * (1.0f / C_) - mu * mu;
    const float rstd = rsqrtf(var + LN_EPS);

    const float4 gv = ((const float4*)g)[tid];
    const float4 be = ((const float4*)beta)[tid];
    float4 o;
    o.x = (v.x - mu) * rstd * gv.x + be.x;
    o.y = (v.y - mu) * rstd * gv.y + be.y;
    o.z = (v.z - mu) * rstd * gv.z + be.z;
    o.w = (v.w - mu) * rstd * gv.w + be.w;
    ((float4*)(out + (size_t)row * C_))[tid] = o;
    if (SPLIT) {
        uint32_t* oh = (uint32_t*)(Oh + (size_t)row * C_);
        oh[2 * tid]     = pack_f16x2(o.x, o.y);
        oh[2 * tid + 1] = pack_f16x2(o.z, o.w);
    }
}

// ---------------- launcher --------------------------------------------------
extern "C" void kernel_launch(void* const* d_in, const int* in_sizes, int n_in,
                              void* d_out, int out_size)
{
    const float* x     = (const float*)d_in[0];
    const float* w_qkv = (const float*)d_in[1];
    const float* b_qkv = (const float*)d_in[2];
    const float* ln1_g = (const float*)d_in[3];
    const float* ln1_b = (const float*)d_in[4];
    const float* w_fc1 = (const float*)d_in[5];
    const float* b_fc1 = (const float*)d_in[6];
    const float* w_fc2 = (const float*)d_in[7];
    const float* b_fc2 = (const float*)d_in[8];
    const float* ln2_g = (const float*)d_in[9];
    const float* ln2_b = (const float*)d_in[10];
    float* out = (float*)d_out;

    float *x1, *mlp;
    __half *qkvh, *ah, *ah2, *b0, *b1, *b2;
    cudaGetSymbolAddress((void**)&x1,   g_x1);
    cudaGetSymbolAddress((void**)&mlp,  g_mlp);
    cudaGetSymbolAddress((void**)&qkvh, g_qkvh);
    cudaGetSymbolAddress((void**)&ah,   g_ah);
    cudaGetSymbolAddress((void**)&ah2,  g_ah2);
    cudaGetSymbolAddress((void**)&b0,   g_b0);
    cudaGetSymbolAddress((void**)&b1,   g_b1);
    cudaGetSymbolAddress((void**)&b2,   g_b2);
    __half* atth = ah2;   // att fp16 lives in g_ah2 until LN1 consumes it

    cudaFuncSetAttribute(gemm_mma<0>, cudaFuncAttributeMaxDynamicSharedMemorySize, GM_SMEM);
    cudaFuncSetAttribute(gemm_mma<1>, cudaFuncAttributeMaxDynamicSharedMemorySize, GM_SMEM);
    cudaFuncSetAttribute(gemm_mma<2>, cudaFuncAttributeMaxDynamicSharedMemorySize, GM_SMEM);
    cudaFuncSetAttribute(attn_tc, cudaFuncAttributeMaxDynamicSharedMemorySize, AT_SMEM);

    // ---- fused prep: all weight transposes + activation round ----
    prep_all<<<11264 + M_ * C_ / 4 / 256, 256>>>(w_qkv, b0, w_fc1, b1, w_fc2, b2, x, ah);

    // ---- QKV = x @ w_qkv + b  -> fp16 (Q scaled QSCALE) ----
    gemm_mma<1><<<dim3(3 * C_ / 128, M_ / 256), 512, GM_SMEM>>>(
        ah, b0, b_qkv, nullptr, qkvh, 3 * C_, C_);

    // ---- attention -> att fp16 (into g_ah2) ----
    attn_tc<<<dim3(T_ / 128, H_, B_), 256, AT_SMEM>>>(qkvh, atth);

    // ---- x1 = LN1(x + att), fused fp16 round for FC1 A ----
    add_ln_kernel<true, true><<<M_, 256>>>(x, atth, ln1_g, ln1_b, x1, ah);

    // ---- h = gelu(x1 @ w_fc1 + b) -> fp16 (overwrites g_ah2) ----
    gemm_mma<2><<<dim3(4 * C_ / 128, M_ / 256), 512, GM_SMEM>>>(
        ah, b1, b_fc1, nullptr, ah2, 4 * C_, C_);

    // ---- mlp = h @ w_fc2 + b (fp32) ----
    gemm_mma<0><<<dim3(C_ / 128, M_ / 256), 512, GM_SMEM>>>(
        ah2, b2, b_fc2, mlp, nullptr, C_, 4 * C_);

    // ---- out = LN2(x1 + mlp) ----
    add_ln_kernel<false, false><<<M_, 256>>>(x1, mlp, ln2_g, ln2_b, out, nullptr);
}